// round 5
// baseline (speedup 1.0000x reference)
#include <cuda_runtime.h>
#include <cuda_fp16.h>
#include <cstdint>
#include <cstddef>

#define B_   512
#define IN_  4096
#define OUT_ 11008

#define NSLAB 128                  // K slabs of 32
#define UNITS_PER_SLAB 22016       // 16-elem units per slab (11008 rows * 2)
#define TOTAL_UNITS (NSLAB * UNITS_PER_SLAB)   // 2,818,048
#define NTILES 688                 // (512/128) * (11008/64)
#define GRID_F 148

// static device scratch (no runtime allocation)
__device__ __align__(1024) __half g_W[(size_t)OUT_ * IN_];
__device__ __align__(1024) __half g_x[(size_t)B_ * IN_];
__device__ unsigned g_ctr;
__device__ unsigned g_slab_done[NSLAB];

// ---------------- helpers ----------------------------------------------------
__device__ __forceinline__ uint32_t smem_u32(const void* p) {
    uint32_t a;
    asm("{ .reg .u64 t; cvta.to.shared.u64 t, %1; cvt.u32.u64 %0, t; }"
        : "=r"(a) : "l"(p));
    return a;
}
__device__ __forceinline__ unsigned ld_acquire(const unsigned* p) {
    unsigned v;
    asm volatile("ld.acquire.gpu.global.u32 %0, [%1];" : "=r"(v) : "l"(p));
    return v;
}
#define BARP() asm volatile("bar.sync 1, 384;" ::: "memory")
#define BARC() asm volatile("bar.sync 2, 128;" ::: "memory")
#define CP16(dst, src) \
    asm volatile("cp.async.cg.shared.global [%0], [%1], 16;" :: "r"(dst), "l"(src))
#define CP_COMMIT() asm volatile("cp.async.commit_group;" ::: "memory")

__device__ __forceinline__ void ldsm_x4(uint32_t* r, uint32_t addr) {
    asm volatile("ldmatrix.sync.aligned.m8n8.x4.shared.b16 {%0,%1,%2,%3}, [%4];"
                 : "=r"(r[0]), "=r"(r[1]), "=r"(r[2]), "=r"(r[3]) : "r"(addr));
}
__device__ __forceinline__ void mma16816(float* c, const uint32_t* a, const uint32_t* b) {
    asm volatile(
        "mma.sync.aligned.m16n8k16.row.col.f32.f16.f16.f32 "
        "{%0,%1,%2,%3}, {%4,%5,%6,%7}, {%8,%9}, {%0,%1,%2,%3};\n"
        : "+f"(c[0]), "+f"(c[1]), "+f"(c[2]), "+f"(c[3])
        : "r"(a[0]), "r"(a[1]), "r"(a[2]), "r"(a[3]), "r"(b[0]), "r"(b[1]));
}

// ---------------- kernel 1: x fp32 -> fp16 + counter reset -------------------
__global__ void xconv_kernel(const float* __restrict__ x) {
    if (blockIdx.x == 0) {
        int t = threadIdx.x;
        if (t < NSLAB) g_slab_done[t] = 0u;
        if (t == NSLAB) g_ctr = 0u;
    }
    const int n4 = (B_ * IN_) / 4;
    int stride = gridDim.x * blockDim.x;
    for (int i = blockIdx.x * blockDim.x + threadIdx.x; i < n4; i += stride) {
        float4 v = reinterpret_cast<const float4*>(x)[i];
        __half2 lo = __floats2half2_rn(v.x, v.y);
        __half2 hi = __floats2half2_rn(v.z, v.w);
        uint2 o;
        o.x = *reinterpret_cast<uint32_t*>(&lo);
        o.y = *reinterpret_cast<uint32_t*>(&hi);
        reinterpret_cast<uint2*>(g_x)[i] = o;
    }
}

// ---------------- fused producer/consumer kernel -----------------------------
#define MT 128
#define NT 64
#define BK 32
#define AS_STRIDE 40

__global__ void __launch_bounds__(512, 1)
fused_kernel(const int* __restrict__ stored, const int* __restrict__ sign,
             const float* __restrict__ lmin_p, const float* __restrict__ lmax_p,
             const float* __restrict__ bias, const float* __restrict__ scale,
             float* __restrict__ out) {
    __shared__ __half sA[2][MT * AS_STRIDE];
    __shared__ __half sB[2][NT * AS_STRIDE];
    __shared__ unsigned lut[512];
    __shared__ unsigned s_base;

    const int tid  = threadIdx.x;
    const int wid  = tid >> 5;
    const int lane = tid & 31;
    const int bid  = blockIdx.x;

    // ---- build LUT (all threads) ----
    {
        float lmin = __ldg(lmin_p);
        float lmax = __ldg(lmax_p);
        if (tid < 511) {
            int s = tid - 255;
            int mag = s < 0 ? -s : s;
            float w = 0.0f;
            if (s != 0) {
                float nrm = (255.0f - (float)mag) * (1.0f / 254.0f);
                w = expf(lmin + nrm * (lmax - lmin));
                if (s < 0) w = -w;
            }
            unsigned hb = (unsigned)__half_as_ushort(__float2half_rn(w));
            lut[tid] = hb | (hb << 16);
        }
    }
    __syncthreads();

    if (wid >= 4) {
        // ================= PRODUCER: dequant, K-slab-major, work stealing ====
        const int ptid = tid - 128;  // 0..383
        for (;;) {
            if (ptid == 0) s_base = atomicAdd(&g_ctr, 384u);
            BARP();
            unsigned base = s_base;
            if (base >= TOTAL_UNITS) break;
            unsigned u = base + (unsigned)ptid;
            if (u < TOTAL_UNITS) {
                unsigned k   = u / UNITS_PER_SLAB;
                unsigned r2  = u - k * UNITS_PER_SLAB;
                unsigned row = r2 >> 1;
                unsigned q   = (r2 & 1u) * 16u;
                size_t flat  = (size_t)row * IN_ + k * BK + q;
                const int4* st = reinterpret_cast<const int4*>(stored + flat);
                const int4* sg = reinterpret_cast<const int4*>(sign + flat);
                int4 a0 = st[0], a1 = st[1], a2 = st[2], a3 = st[3];
                int4 s0 = sg[0], s1 = sg[1], s2 = sg[2], s3 = sg[3];
                uint4 o0, o1;
                o0.x = __byte_perm(lut[s0.x * a0.x + 255], lut[s0.y * a0.y + 255], 0x5410);
                o0.y = __byte_perm(lut[s0.z * a0.z + 255], lut[s0.w * a0.w + 255], 0x5410);
                o0.z = __byte_perm(lut[s1.x * a1.x + 255], lut[s1.y * a1.y + 255], 0x5410);
                o0.w = __byte_perm(lut[s1.z * a1.z + 255], lut[s1.w * a1.w + 255], 0x5410);
                o1.x = __byte_perm(lut[s2.x * a2.x + 255], lut[s2.y * a2.y + 255], 0x5410);
                o1.y = __byte_perm(lut[s2.z * a2.z + 255], lut[s2.w * a2.w + 255], 0x5410);
                o1.z = __byte_perm(lut[s3.x * a3.x + 255], lut[s3.y * a3.y + 255], 0x5410);
                o1.w = __byte_perm(lut[s3.z * a3.z + 255], lut[s3.w * a3.w + 255], 0x5410);
                uint4* dst = reinterpret_cast<uint4*>(g_W + flat);
                dst[0] = o0;
                dst[1] = o1;
            }
            __threadfence();
            BARP();
            if (ptid == 0) {
                unsigned end = base + 384u;
                if (end > TOTAL_UNITS) end = TOTAL_UNITS;
                unsigned k0 = base / UNITS_PER_SLAB;
                unsigned k1 = (end - 1u) / UNITS_PER_SLAB;
                for (unsigned k = k0; k <= k1; k++) {
                    unsigned lo = k * UNITS_PER_SLAB;      if (lo < base) lo = base;
                    unsigned hi = (k + 1u) * UNITS_PER_SLAB; if (hi > end) hi = end;
                    atomicAdd(&g_slab_done[k], hi - lo);
                }
            }
        }
        return;
    }

    // ================= CONSUMER: 4 warps, tile 128x64, persistent ============
    // ldmatrix offsets (tile-independent)
    const int lr = lane & 7;
    const int lj = lane >> 3;
    uint32_t aBase[2], bBase[2];
#pragma unroll
    for (int s = 0; s < 2; s++) {
        aBase[s] = smem_u32(sA[s]);
        bBase[s] = smem_u32(sB[s]);
    }
    uint32_t aOff[2][2], bOff[2][4];
#pragma unroll
    for (int ks = 0; ks < 2; ks++) {
        int kk = ks * 16;
#pragma unroll
        for (int mf = 0; mf < 2; mf++) {
            int row = wid * 32 + mf * 16 + lr + (lj & 1) * 8;
            int col = kk + (lj >> 1) * 8;
            aOff[ks][mf] = (uint32_t)(row * AS_STRIDE + col) * 2;
        }
#pragma unroll
        for (int nh = 0; nh < 4; nh++) {
            int nrow = nh * 16 + lr + (lj >> 1) * 8;
            int col  = kk + (lj & 1) * 8;
            bOff[ks][nh] = (uint32_t)(nrow * AS_STRIDE + col) * 2;
        }
    }

    // fill geometry: A 4x16B, B 2x16B per thread per chunk
    int arow[4], acol[4], brow[2], bcol[2];
    uint32_t adst[2][4], bdst[2][2];
#pragma unroll
    for (int j = 0; j < 4; j++) {
        int idx = j * 128 + tid;
        arow[j] = idx >> 2;
        acol[j] = (idx & 3) * 8;
#pragma unroll
        for (int s = 0; s < 2; s++)
            adst[s][j] = smem_u32(&sA[s][arow[j] * AS_STRIDE + acol[j]]);
    }
#pragma unroll
    for (int j = 0; j < 2; j++) {
        int idx = j * 128 + tid;
        brow[j] = idx >> 2;
        bcol[j] = (idx & 3) * 8;
#pragma unroll
        for (int s = 0; s < 2; s++)
            bdst[s][j] = smem_u32(&sB[s][brow[j] * AS_STRIDE + bcol[j]]);
    }

    int kw = 0;  // slab watermark
    const int lq = lane >> 2;
    const int lp = lane & 3;

    for (int t = bid; t < NTILES; t += GRID_F) {
        const int ntile = t % 172;
        const int mtile = t / 172;

        const __half* Abase = g_x + (size_t)(mtile * MT) * IN_;
        const __half* Bbase = g_W + (size_t)(ntile * NT) * IN_;

        float acc[2][8][4];
#pragma unroll
        for (int a = 0; a < 2; a++)
#pragma unroll
            for (int b = 0; b < 8; b++)
#pragma unroll
                for (int q = 0; q < 4; q++) acc[a][b][q] = 0.0f;

        auto wait_slab = [&](int k) {
            if (k >= kw) {
                while (ld_acquire(&g_slab_done[k]) < UNITS_PER_SLAB)
                    asm volatile("nanosleep.u32 128;");
                kw = k + 1;
            }
        };
        auto fill = [&](int chunk, int s) {
            int k0 = chunk * BK;
#pragma unroll
            for (int j = 0; j < 4; j++)
                CP16(adst[s][j], Abase + (size_t)arow[j] * IN_ + k0 + acol[j]);
#pragma unroll
            for (int j = 0; j < 2; j++)
                CP16(bdst[s][j], Bbase + (size_t)brow[j] * IN_ + k0 + bcol[j]);
            CP_COMMIT();
        };

        wait_slab(0); fill(0, 0);
        wait_slab(1); fill(1, 1);

        for (int i = 0; i < NSLAB; i++) {
            const int s = i & 1;
            if (i < NSLAB - 1) asm volatile("cp.async.wait_group 1;" ::: "memory");
            else               asm volatile("cp.async.wait_group 0;" ::: "memory");
            BARC();

#pragma unroll
            for (int ks = 0; ks < 2; ks++) {
                uint32_t a_frag[2][4];
                uint32_t b_frag[8][2];
#pragma unroll
                for (int mf = 0; mf < 2; mf++)
                    ldsm_x4(a_frag[mf], aBase[s] + aOff[ks][mf]);
#pragma unroll
                for (int nh = 0; nh < 4; nh++) {
                    uint32_t r[4];
                    ldsm_x4(r, bBase[s] + bOff[ks][nh]);
                    b_frag[2 * nh][0]     = r[0];
                    b_frag[2 * nh][1]     = r[1];
                    b_frag[2 * nh + 1][0] = r[2];
                    b_frag[2 * nh + 1][1] = r[3];
                }
#pragma unroll
                for (int mf = 0; mf < 2; mf++)
#pragma unroll
                    for (int nf = 0; nf < 8; nf++)
                        mma16816(acc[mf][nf], a_frag[mf], b_frag[nf]);
            }

            BARC();
            if (i + 2 < NSLAB) { wait_slab(i + 2); fill(i + 2, s); }
        }

        // epilogue: (acc + bias) * scale
#pragma unroll
        for (int mf = 0; mf < 2; mf++) {
            int grow = mtile * MT + wid * 32 + mf * 16 + lq;
#pragma unroll
            for (int nf = 0; nf < 8; nf++) {
                int gcol = ntile * NT + nf * 8 + 2 * lp;
                float b0 = __ldg(bias + gcol),  b1 = __ldg(bias + gcol + 1);
                float c0 = __ldg(scale + gcol), c1 = __ldg(scale + gcol + 1);
                size_t base = (size_t)grow * OUT_ + gcol;
                float2 v0, v1;
                v0.x = (acc[mf][nf][0] + b0) * c0;
                v0.y = (acc[mf][nf][1] + b1) * c1;
                v1.x = (acc[mf][nf][2] + b0) * c0;
                v1.y = (acc[mf][nf][3] + b1) * c1;
                *reinterpret_cast<float2*>(out + base)            = v0;
                *reinterpret_cast<float2*>(out + base + 8 * OUT_) = v1;
            }
        }
        BARC();   // smem safe for next tile
    }
}

// ---------------- launch -----------------------------------------------------
extern "C" void kernel_launch(void* const* d_in, const int* in_sizes, int n_in,
                              void* d_out, int out_size) {
    const float* x      = (const float*)d_in[0];
    const int*   stored = (const int*)d_in[1];
    const int*   sign   = (const int*)d_in[2];
    const float* lmin   = (const float*)d_in[3];
    const float* lmax   = (const float*)d_in[4];
    const float* scale  = (const float*)d_in[5];
    const float* bias   = (const float*)d_in[6];
    float* out = (float*)d_out;

    xconv_kernel<<<512, 256>>>(x);
    fused_kernel<<<GRID_F, 512>>>(stored, sign, lmin, lmax, bias, scale, out);
}

// round 6
// speedup vs baseline: 1.8030x; 1.8030x over previous
#include <cuda_runtime.h>
#include <cuda_fp16.h>
#include <cstdint>
#include <cstddef>

#define B_   512
#define IN_  4096
#define OUT_ 11008

#define NT      64
#define NTILES  172          // OUT / NT
#define KSPLIT  2
#define KHALF   2048         // IN / KSPLIT
#define BK      64
#define NCH     32           // KHALF / BK
#define AS      72           // smem row stride in halves (64 + 8 pad)

// static device scratch (no runtime allocation)
__device__ __align__(1024) __half g_x[(size_t)B_ * IN_];

// ---------------- helpers ----------------------------------------------------
__device__ __forceinline__ uint32_t smem_u32(const void* p) {
    uint32_t a;
    asm("{ .reg .u64 t; cvta.to.shared.u64 t, %1; cvt.u32.u64 %0, t; }"
        : "=r"(a) : "l"(p));
    return a;
}
#define CP16(dst, src) \
    asm volatile("cp.async.cg.shared.global [%0], [%1], 16;" :: "r"(dst), "l"(src))
#define CP_COMMIT() asm volatile("cp.async.commit_group;" ::: "memory")

__device__ __forceinline__ void ldsm_x4(uint32_t* r, uint32_t addr) {
    asm volatile("ldmatrix.sync.aligned.m8n8.x4.shared.b16 {%0,%1,%2,%3}, [%4];"
                 : "=r"(r[0]), "=r"(r[1]), "=r"(r[2]), "=r"(r[3]) : "r"(addr));
}
__device__ __forceinline__ void mma16816(float* c, const uint32_t* a, const uint32_t* b) {
    asm volatile(
        "mma.sync.aligned.m16n8k16.row.col.f32.f16.f16.f32 "
        "{%0,%1,%2,%3}, {%4,%5,%6,%7}, {%8,%9}, {%0,%1,%2,%3};\n"
        : "+f"(c[0]), "+f"(c[1]), "+f"(c[2]), "+f"(c[3])
        : "r"(a[0]), "r"(a[1]), "r"(a[2]), "r"(a[3]), "r"(b[0]), "r"(b[1]));
}
__device__ __forceinline__ void red_add_f32(float* p, float v) {
    asm volatile("red.global.add.f32 [%0], %1;" :: "l"(p), "f"(v) : "memory");
}

// ---------------- kernel 0: zero the output ---------------------------------
__global__ void zero_kernel(float* __restrict__ out) {
    const int n4 = (B_ * OUT_) / 4;
    int stride = gridDim.x * blockDim.x;
    float4 z = make_float4(0.f, 0.f, 0.f, 0.f);
    for (int i = blockIdx.x * blockDim.x + threadIdx.x; i < n4; i += stride)
        reinterpret_cast<float4*>(out)[i] = z;
}

// ---------------- kernel 1: x fp32 -> fp16 -----------------------------------
__global__ void xconv_kernel(const float* __restrict__ x) {
    const int n4 = (B_ * IN_) / 4;
    int stride = gridDim.x * blockDim.x;
    for (int i = blockIdx.x * blockDim.x + threadIdx.x; i < n4; i += stride) {
        float4 v = reinterpret_cast<const float4*>(x)[i];
        __half2 lo = __floats2half2_rn(v.x, v.y);
        __half2 hi = __floats2half2_rn(v.z, v.w);
        uint2 o;
        o.x = *reinterpret_cast<uint32_t*>(&lo);
        o.y = *reinterpret_cast<uint32_t*>(&hi);
        reinterpret_cast<uint2*>(g_x)[i] = o;
    }
}

// ---------------- fused dequant + GEMM kernel --------------------------------
// Tile: M=512 (all rows), N=64, K=2048 (half). Grid = 172 ntiles x 2 khalves.
// smem: A 2 stages (512x72 halves), B 2 stages (64x72 halves), lut 512 u32.
static constexpr uint32_t ASZ_B = 512 * AS * 2;          // 73728
static constexpr uint32_t BSZ_B = 64 * AS * 2;           // 9216
static constexpr uint32_t SMEM_REQ = 2 * ASZ_B + 2 * BSZ_B + 2048;  // 167936

__global__ void __launch_bounds__(512, 1)
fused_kernel(const int* __restrict__ stored, const int* __restrict__ sign,
             const float* __restrict__ lmin_p, const float* __restrict__ lmax_p,
             const float* __restrict__ bias, const float* __restrict__ scale,
             float* __restrict__ out) {
    extern __shared__ char smem[];
    const uint32_t sA0 = smem_u32(smem);
    const uint32_t sB0 = sA0 + 2 * ASZ_B;
    unsigned* lut = reinterpret_cast<unsigned*>(smem + 2 * ASZ_B + 2 * BSZ_B);

    const int tid  = threadIdx.x;
    const int wid  = tid >> 5;
    const int lane = tid & 31;
    const int ntile = blockIdx.x % NTILES;
    const int kh    = blockIdx.x / NTILES;
    const int n0    = ntile * NT;
    const int k0    = kh * KHALF;

    // ---- build LUT ----
    {
        float lmin = __ldg(lmin_p);
        float lmax = __ldg(lmax_p);
        if (tid < 511) {
            int s = tid - 255;
            int mag = s < 0 ? -s : s;
            float w = 0.0f;
            if (s != 0) {
                float nrm = (255.0f - (float)mag) * (1.0f / 254.0f);
                w = expf(lmin + nrm * (lmax - lmin));
                if (s < 0) w = -w;
            }
            unsigned hb = (unsigned)__half_as_ushort(__float2half_rn(w));
            lut[tid] = hb | (hb << 16);
        }
    }
    __syncthreads();

    // ---- A fill geometry: 8 x 16B per thread per chunk ----
    int arow[8], acol[8];
    uint32_t adst[2][8];
#pragma unroll
    for (int j = 0; j < 8; j++) {
        int idx = j * 512 + tid;          // 0..4095
        arow[j] = idx >> 3;               // 0..511
        acol[j] = (idx & 7) * 8;          // halves
#pragma unroll
        for (int s = 0; s < 2; s++)
            adst[s][j] = sA0 + s * ASZ_B + (uint32_t)(arow[j] * AS + acol[j]) * 2;
    }
    auto fillA = [&](int chunk, int s) {
        const __half* base = g_x + k0 + chunk * BK;
#pragma unroll
        for (int j = 0; j < 8; j++)
            CP16(adst[s][j], base + (size_t)arow[j] * IN_ + acol[j]);
        CP_COMMIT();
    };

    // ---- B dequant geometry: 8 elems per thread per chunk ----
    const int drow = tid >> 3;            // 0..63
    const int dkq  = (tid & 7) * 8;       // k offset
    const int* stp = stored + (size_t)(n0 + drow) * IN_ + k0 + dkq;
    const int* sgp = sign   + (size_t)(n0 + drow) * IN_ + k0 + dkq;
    uint32_t bdst[2];
#pragma unroll
    for (int s = 0; s < 2; s++)
        bdst[s] = sB0 + s * BSZ_B + (uint32_t)(drow * AS + dkq) * 2;

    int4 st0, st1, sg0, sg1;
    auto loadB = [&](int chunk) {
        const int4* a = reinterpret_cast<const int4*>(stp + chunk * BK);
        const int4* b = reinterpret_cast<const int4*>(sgp + chunk * BK);
        st0 = a[0]; st1 = a[1];
        sg0 = b[0]; sg1 = b[1];
    };
    auto stsB = [&](int s) {
        unsigned l0 = lut[sg0.x * st0.x + 255];
        unsigned l1 = lut[sg0.y * st0.y + 255];
        unsigned l2 = lut[sg0.z * st0.z + 255];
        unsigned l3 = lut[sg0.w * st0.w + 255];
        unsigned l4 = lut[sg1.x * st1.x + 255];
        unsigned l5 = lut[sg1.y * st1.y + 255];
        unsigned l6 = lut[sg1.z * st1.z + 255];
        unsigned l7 = lut[sg1.w * st1.w + 255];
        uint32_t w0 = __byte_perm(l0, l1, 0x5410);
        uint32_t w1 = __byte_perm(l2, l3, 0x5410);
        uint32_t w2 = __byte_perm(l4, l5, 0x5410);
        uint32_t w3 = __byte_perm(l6, l7, 0x5410);
        asm volatile("st.shared.v4.b32 [%0], {%1,%2,%3,%4};"
                     :: "r"(bdst[s]), "r"(w0), "r"(w1), "r"(w2), "r"(w3) : "memory");
    };

    // ---- ldmatrix offsets ----
    const int wm = wid >> 1;              // 0..7 -> rows wm*64
    const int wn = wid & 1;               // 0..1 -> cols wn*32
    const int lr = lane & 7;
    const int lj = lane >> 3;
    uint32_t aOff[4][4], bOff[4][2];
#pragma unroll
    for (int ks = 0; ks < 4; ks++) {
        int kk = ks * 16;
#pragma unroll
        for (int mf = 0; mf < 4; mf++) {
            int row = wm * 64 + mf * 16 + lr + (lj & 1) * 8;
            int col = kk + (lj >> 1) * 8;
            aOff[ks][mf] = (uint32_t)(row * AS + col) * 2;
        }
#pragma unroll
        for (int nh = 0; nh < 2; nh++) {
            int nrow = wn * 32 + nh * 16 + lr + (lj >> 1) * 8;
            int col  = kk + (lj & 1) * 8;
            bOff[ks][nh] = (uint32_t)(nrow * AS + col) * 2;
        }
    }

    float acc[4][4][4];
#pragma unroll
    for (int a = 0; a < 4; a++)
#pragma unroll
        for (int b = 0; b < 4; b++)
#pragma unroll
            for (int q = 0; q < 4; q++) acc[a][b][q] = 0.0f;

    // ---- prologue ----
    loadB(0); stsB(0);
    fillA(0, 0);
    loadB(1);
    fillA(1, 1);

    // ---- main loop ----
    for (int i = 0; i < NCH; i++) {
        const int s = i & 1;
        if (i < NCH - 1) asm volatile("cp.async.wait_group 1;" ::: "memory");
        else             asm volatile("cp.async.wait_group 0;" ::: "memory");
        __syncthreads();                       // A(s) + B(s) visible

        uint32_t aBase = sA0 + s * ASZ_B;
        uint32_t bBase = sB0 + s * BSZ_B;
#pragma unroll
        for (int ks = 0; ks < 4; ks++) {
            uint32_t a_frag[4][4];
            uint32_t b_frag[4][2];
#pragma unroll
            for (int mf = 0; mf < 4; mf++)
                ldsm_x4(a_frag[mf], aBase + aOff[ks][mf]);
#pragma unroll
            for (int nh = 0; nh < 2; nh++) {
                uint32_t r[4];
                ldsm_x4(r, bBase + bOff[ks][nh]);
                b_frag[2 * nh][0]     = r[0];
                b_frag[2 * nh][1]     = r[1];
                b_frag[2 * nh + 1][0] = r[2];
                b_frag[2 * nh + 1][1] = r[3];
            }
#pragma unroll
            for (int mf = 0; mf < 4; mf++)
#pragma unroll
                for (int nf = 0; nf < 4; nf++)
                    mma16816(acc[mf][nf], a_frag[mf], b_frag[nf]);
        }

        __syncthreads();                       // stage s free for refill
        if (i + 1 < NCH) stsB(s ^ 1);          // B(i+1) regs -> stage s^1
        if (i + 2 < NCH) {
            loadB(i + 2);                      // prefetch B(i+2) regs
            fillA(i + 2, s);                   // A(i+2) -> stage s
        }
    }

    // ---- epilogue: red.add (acc [+bias]) * scale ----
    const int lq = lane >> 2;
    const int lp = lane & 3;
#pragma unroll
    for (int mf = 0; mf < 4; mf++) {
        int grow = wm * 64 + mf * 16 + lq;
#pragma unroll
        for (int nf = 0; nf < 4; nf++) {
            int gcol = n0 + wn * 32 + nf * 8 + 2 * lp;
            float c0 = __ldg(scale + gcol), c1 = __ldg(scale + gcol + 1);
            float b0 = 0.f, b1 = 0.f;
            if (kh == 0) { b0 = __ldg(bias + gcol); b1 = __ldg(bias + gcol + 1); }
            float* p = out + (size_t)grow * OUT_ + gcol;
            red_add_f32(p,                (acc[mf][nf][0] + b0) * c0);
            red_add_f32(p + 1,            (acc[mf][nf][1] + b1) * c1);
            red_add_f32(p + 8 * OUT_,     (acc[mf][nf][2]) * c0);
            red_add_f32(p + 8 * OUT_ + 1, (acc[mf][nf][3]) * c1);
        }
    }
}

// ---------------- launch -----------------------------------------------------
extern "C" void kernel_launch(void* const* d_in, const int* in_sizes, int n_in,
                              void* d_out, int out_size) {
    const float* x      = (const float*)d_in[0];
    const int*   stored = (const int*)d_in[1];
    const int*   sign   = (const int*)d_in[2];
    const float* lmin   = (const float*)d_in[3];
    const float* lmax   = (const float*)d_in[4];
    const float* scale  = (const float*)d_in[5];
    const float* bias   = (const float*)d_in[6];
    float* out = (float*)d_out;

    cudaFuncSetAttribute(fused_kernel, cudaFuncAttributeMaxDynamicSharedMemorySize,
                         (int)SMEM_REQ);

    zero_kernel<<<688, 256>>>(out);
    xconv_kernel<<<512, 256>>>(x);
    fused_kernel<<<NTILES * KSPLIT, 512, SMEM_REQ>>>(stored, sign, lmin, lmax,
                                                     bias, scale, out);
}

// round 7
// speedup vs baseline: 2.0343x; 1.1283x over previous
#include <cuda_runtime.h>
#include <cuda_fp16.h>
#include <cstdint>
#include <cstddef>

#define B_   512
#define IN_  4096
#define OUT_ 11008

#define NT      64
#define NTILES  172          // OUT / NT
#define KSPLIT  4
#define KPART   1024         // IN / KSPLIT
#define BK      64
#define NCH     16           // KPART / BK
#define AS      72           // smem row stride in halves (64 + 8 pad)
#define PLANE   ((size_t)B_ * OUT_)

// static device scratch (no runtime allocation)
__device__ __align__(1024) __half g_x[(size_t)B_ * IN_];
__device__ __align__(1024) float  g_part[KSPLIT * PLANE];   // 90 MB partials

// ---------------- helpers ----------------------------------------------------
__device__ __forceinline__ uint32_t smem_u32(const void* p) {
    uint32_t a;
    asm("{ .reg .u64 t; cvta.to.shared.u64 t, %1; cvt.u32.u64 %0, t; }"
        : "=r"(a) : "l"(p));
    return a;
}
#define CP16(dst, src) \
    asm volatile("cp.async.cg.shared.global [%0], [%1], 16;" :: "r"(dst), "l"(src))
#define CP_COMMIT() asm volatile("cp.async.commit_group;" ::: "memory")

__device__ __forceinline__ void ldsm_x4(uint32_t* r, uint32_t addr) {
    asm volatile("ldmatrix.sync.aligned.m8n8.x4.shared.b16 {%0,%1,%2,%3}, [%4];"
                 : "=r"(r[0]), "=r"(r[1]), "=r"(r[2]), "=r"(r[3]) : "r"(addr));
}
__device__ __forceinline__ void mma16816(float* c, const uint32_t* a, const uint32_t* b) {
    asm volatile(
        "mma.sync.aligned.m16n8k16.row.col.f32.f16.f16.f32 "
        "{%0,%1,%2,%3}, {%4,%5,%6,%7}, {%8,%9}, {%0,%1,%2,%3};\n"
        : "+f"(c[0]), "+f"(c[1]), "+f"(c[2]), "+f"(c[3])
        : "r"(a[0]), "r"(a[1]), "r"(a[2]), "r"(a[3]), "r"(b[0]), "r"(b[1]));
}

// ---------------- kernel 1: x fp32 -> fp16 -----------------------------------
__global__ void xconv_kernel(const float* __restrict__ x) {
    const int n4 = (B_ * IN_) / 4;
    int stride = gridDim.x * blockDim.x;
    for (int i = blockIdx.x * blockDim.x + threadIdx.x; i < n4; i += stride) {
        float4 v = reinterpret_cast<const float4*>(x)[i];
        __half2 lo = __floats2half2_rn(v.x, v.y);
        __half2 hi = __floats2half2_rn(v.z, v.w);
        uint2 o;
        o.x = *reinterpret_cast<uint32_t*>(&lo);
        o.y = *reinterpret_cast<uint32_t*>(&hi);
        reinterpret_cast<uint2*>(g_x)[i] = o;
    }
}

// ---------------- fused dequant + GEMM kernel --------------------------------
// Tile: M=512 (all rows), N=64, K=1024 (quarter). Grid = 172 x 4.
static constexpr uint32_t ASZ_B = 512 * AS * 2;          // 73728
static constexpr uint32_t BSZ_B = 64 * AS * 2;           // 9216
static constexpr uint32_t SMEM_REQ = 2 * ASZ_B + 2 * BSZ_B + 2048;  // 167936

__global__ void __launch_bounds__(512, 1)
fused_kernel(const int* __restrict__ stored, const int* __restrict__ sign,
             const float* __restrict__ lmin_p, const float* __restrict__ lmax_p) {
    extern __shared__ char smem[];
    const uint32_t sA0 = smem_u32(smem);
    const uint32_t sB0 = sA0 + 2 * ASZ_B;
    unsigned* lut = reinterpret_cast<unsigned*>(smem + 2 * ASZ_B + 2 * BSZ_B);

    const int tid  = threadIdx.x;
    const int wid  = tid >> 5;
    const int lane = tid & 31;
    const int ntile = blockIdx.x % NTILES;
    const int kh    = blockIdx.x / NTILES;
    const int n0    = ntile * NT;
    const int k0    = kh * KPART;

    // ---- build LUT ----
    {
        float lmin = __ldg(lmin_p);
        float lmax = __ldg(lmax_p);
        if (tid < 511) {
            int s = tid - 255;
            int mag = s < 0 ? -s : s;
            float w = 0.0f;
            if (s != 0) {
                float nrm = (255.0f - (float)mag) * (1.0f / 254.0f);
                w = expf(lmin + nrm * (lmax - lmin));
                if (s < 0) w = -w;
            }
            unsigned hb = (unsigned)__half_as_ushort(__float2half_rn(w));
            lut[tid] = hb | (hb << 16);
        }
    }
    __syncthreads();

    // ---- A fill geometry: 8 x 16B per thread per chunk ----
    int arow[8], acol[8];
    uint32_t adst[2][8];
#pragma unroll
    for (int j = 0; j < 8; j++) {
        int idx = j * 512 + tid;          // 0..4095
        arow[j] = idx >> 3;               // 0..511
        acol[j] = (idx & 7) * 8;          // halves
#pragma unroll
        for (int s = 0; s < 2; s++)
            adst[s][j] = sA0 + s * ASZ_B + (uint32_t)(arow[j] * AS + acol[j]) * 2;
    }
    auto fillA = [&](int chunk, int s) {
        const __half* base = g_x + k0 + chunk * BK;
#pragma unroll
        for (int j = 0; j < 8; j++)
            CP16(adst[s][j], base + (size_t)arow[j] * IN_ + acol[j]);
        CP_COMMIT();
    };

    // ---- B dequant geometry: 8 elems per thread per chunk ----
    const int drow = tid >> 3;            // 0..63
    const int dkq  = (tid & 7) * 8;       // k offset
    const int* stp = stored + (size_t)(n0 + drow) * IN_ + k0 + dkq;
    const int* sgp = sign   + (size_t)(n0 + drow) * IN_ + k0 + dkq;
    uint32_t bdst[2];
#pragma unroll
    for (int s = 0; s < 2; s++)
        bdst[s] = sB0 + s * BSZ_B + (uint32_t)(drow * AS + dkq) * 2;

    int4 st0, st1, sg0, sg1;
    auto loadB = [&](int chunk) {
        const int4* a = reinterpret_cast<const int4*>(stp + chunk * BK);
        const int4* b = reinterpret_cast<const int4*>(sgp + chunk * BK);
        st0 = a[0]; st1 = a[1];
        sg0 = b[0]; sg1 = b[1];
    };
    auto stsB = [&](int s) {
        unsigned l0 = lut[sg0.x * st0.x + 255];
        unsigned l1 = lut[sg0.y * st0.y + 255];
        unsigned l2 = lut[sg0.z * st0.z + 255];
        unsigned l3 = lut[sg0.w * st0.w + 255];
        unsigned l4 = lut[sg1.x * st1.x + 255];
        unsigned l5 = lut[sg1.y * st1.y + 255];
        unsigned l6 = lut[sg1.z * st1.z + 255];
        unsigned l7 = lut[sg1.w * st1.w + 255];
        uint32_t w0 = __byte_perm(l0, l1, 0x5410);
        uint32_t w1 = __byte_perm(l2, l3, 0x5410);
        uint32_t w2 = __byte_perm(l4, l5, 0x5410);
        uint32_t w3 = __byte_perm(l6, l7, 0x5410);
        asm volatile("st.shared.v4.b32 [%0], {%1,%2,%3,%4};"
                     :: "r"(bdst[s]), "r"(w0), "r"(w1), "r"(w2), "r"(w3) : "memory");
    };

    // ---- ldmatrix offsets ----
    const int wm = wid >> 1;              // 0..7 -> rows wm*64
    const int wn = wid & 1;               // 0..1 -> cols wn*32
    const int lr = lane & 7;
    const int lj = lane >> 3;
    uint32_t aOff[4][4], bOff[4][2];
#pragma unroll
    for (int ks = 0; ks < 4; ks++) {
        int kk = ks * 16;
#pragma unroll
        for (int mf = 0; mf < 4; mf++) {
            int row = wm * 64 + mf * 16 + lr + (lj & 1) * 8;
            int col = kk + (lj >> 1) * 8;
            aOff[ks][mf] = (uint32_t)(row * AS + col) * 2;
        }
#pragma unroll
        for (int nh = 0; nh < 2; nh++) {
            int nrow = wn * 32 + nh * 16 + lr + (lj >> 1) * 8;
            int col  = kk + (lj & 1) * 8;
            bOff[ks][nh] = (uint32_t)(nrow * AS + col) * 2;
        }
    }

    float acc[4][4][4];
#pragma unroll
    for (int a = 0; a < 4; a++)
#pragma unroll
        for (int b = 0; b < 4; b++)
#pragma unroll
            for (int q = 0; q < 4; q++) acc[a][b][q] = 0.0f;

    // ---- prologue ----
    loadB(0); stsB(0);
    fillA(0, 0);
    loadB(1);
    fillA(1, 1);

    // ---- main loop ----
    for (int i = 0; i < NCH; i++) {
        const int s = i & 1;
        if (i < NCH - 1) asm volatile("cp.async.wait_group 1;" ::: "memory");
        else             asm volatile("cp.async.wait_group 0;" ::: "memory");
        __syncthreads();                       // A(s) + B(s) visible

        uint32_t aBase = sA0 + s * ASZ_B;
        uint32_t bBase = sB0 + s * BSZ_B;
#pragma unroll
        for (int ks = 0; ks < 4; ks++) {
            uint32_t a_frag[4][4];
            uint32_t b_frag[4][2];
#pragma unroll
            for (int mf = 0; mf < 4; mf++)
                ldsm_x4(a_frag[mf], aBase + aOff[ks][mf]);
#pragma unroll
            for (int nh = 0; nh < 2; nh++) {
                uint32_t r[4];
                ldsm_x4(r, bBase + bOff[ks][nh]);
                b_frag[2 * nh][0]     = r[0];
                b_frag[2 * nh][1]     = r[1];
                b_frag[2 * nh + 1][0] = r[2];
                b_frag[2 * nh + 1][1] = r[3];
            }
#pragma unroll
            for (int mf = 0; mf < 4; mf++)
#pragma unroll
                for (int nf = 0; nf < 4; nf++)
                    mma16816(acc[mf][nf], a_frag[mf], b_frag[nf]);
        }

        __syncthreads();                       // stage s free for refill
        if (i + 1 < NCH) stsB(s ^ 1);          // B(i+1) regs -> stage s^1
        if (i + 2 < NCH) {
            loadB(i + 2);                      // prefetch B(i+2) regs
            fillA(i + 2, s);                   // A(i+2) -> stage s
        }
    }

    // ---- epilogue: plain float2 stores into the partial plane ----
    float* plane = g_part + (size_t)kh * PLANE;
    const int lq = lane >> 2;
    const int lp = lane & 3;
#pragma unroll
    for (int mf = 0; mf < 4; mf++) {
        int grow = wm * 64 + mf * 16 + lq;
#pragma unroll
        for (int nf = 0; nf < 4; nf++) {
            int gcol = n0 + wn * 32 + nf * 8 + 2 * lp;
            float* p = plane + (size_t)grow * OUT_ + gcol;
            float2 v0, v1;
            v0.x = acc[mf][nf][0];
            v0.y = acc[mf][nf][1];
            v1.x = acc[mf][nf][2];
            v1.y = acc[mf][nf][3];
            *reinterpret_cast<float2*>(p)            = v0;
            *reinterpret_cast<float2*>(p + 8 * OUT_) = v1;
        }
    }
}

// ---------------- reduce kernel: out = (sum(partials) + bias) * scale --------
__global__ void reduce_kernel(const float* __restrict__ bias,
                              const float* __restrict__ scale,
                              float* __restrict__ out) {
    const int n4 = (int)(PLANE / 4);
    int stride = gridDim.x * blockDim.x;
    for (int i = blockIdx.x * blockDim.x + threadIdx.x; i < n4; i += stride) {
        size_t e = (size_t)i * 4;
        int col = (int)(e % OUT_);
        float4 p0 = __ldg(reinterpret_cast<const float4*>(g_part + e));
        float4 p1 = __ldg(reinterpret_cast<const float4*>(g_part + PLANE + e));
        float4 p2 = __ldg(reinterpret_cast<const float4*>(g_part + 2 * PLANE + e));
        float4 p3 = __ldg(reinterpret_cast<const float4*>(g_part + 3 * PLANE + e));
        float4 b  = __ldg(reinterpret_cast<const float4*>(bias + col));
        float4 c  = __ldg(reinterpret_cast<const float4*>(scale + col));
        float4 r;
        r.x = (p0.x + p1.x + p2.x + p3.x + b.x) * c.x;
        r.y = (p0.y + p1.y + p2.y + p3.y + b.y) * c.y;
        r.z = (p0.z + p1.z + p2.z + p3.z + b.z) * c.z;
        r.w = (p0.w + p1.w + p2.w + p3.w + b.w) * c.w;
        reinterpret_cast<float4*>(out)[i] = r;
    }
}

// ---------------- launch -----------------------------------------------------
extern "C" void kernel_launch(void* const* d_in, const int* in_sizes, int n_in,
                              void* d_out, int out_size) {
    const float* x      = (const float*)d_in[0];
    const int*   stored = (const int*)d_in[1];
    const int*   sign   = (const int*)d_in[2];
    const float* lmin   = (const float*)d_in[3];
    const float* lmax   = (const float*)d_in[4];
    const float* scale  = (const float*)d_in[5];
    const float* bias   = (const float*)d_in[6];
    float* out = (float*)d_out;

    cudaFuncSetAttribute(fused_kernel, cudaFuncAttributeMaxDynamicSharedMemorySize,
                         (int)SMEM_REQ);

    xconv_kernel<<<512, 256>>>(x);
    fused_kernel<<<NTILES * KSPLIT, 512, SMEM_REQ>>>(stored, sign, lmin, lmax);
    reduce_kernel<<<1024, 256>>>(bias, scale, out);
}